// round 10
// baseline (speedup 1.0000x reference)
#include <cuda_runtime.h>
#include <cuda_bf16.h>

// ObjCondensationLoss — single fused persistent kernel (D==3 fast path).
// Inputs: x (N*3 f32), beta (N f32), y (N i32), K (i32), S_b (f32), q_min (f32)
// Output: scalar f32 loss.
//
// Invariant: all __device__ globals below are ZERO at kernel entry (zero at
// module load; the finalizing block restores zeros before exit each call).

#define KMAX    1024
#define TB_MAIN 256
#define NBLK    296    // 2 blocks/SM, guaranteed by __launch_bounds__(TB_MAIN, 2)
#define THIT    3      // hits per thread per warp-item (amortizes table LDS)

typedef unsigned long long ull;

// pack = (beta_bits << 32) | (0xFFFFFFFF - i). beta>0 => float-bit order == value
// order; atanh monotone => argmax(q) == argmax(beta); tie -> smallest index.
__device__ ull      g_pack[KMAX];
__device__ double   g_sum_bg;      // sum beta over background hits
__device__ double   g_cnt_bg;      // N_b
__device__ double   g_sum_perhit;  // sum(per_hit * q_i)
__device__ unsigned g_bar_cnt;     // grid barrier counter
__device__ unsigned g_done;        // finalize counter

// ---------- f32x2 packed helpers ----------
__device__ __forceinline__ ull pack2(float lo, float hi) {
    ull r; asm("mov.b64 %0, {%1, %2};" : "=l"(r) : "f"(lo), "f"(hi)); return r;
}
__device__ __forceinline__ void unpack2(ull v, float& lo, float& hi) {
    asm("mov.b64 {%0, %1}, %2;" : "=f"(lo), "=f"(hi) : "l"(v));
}
__device__ __forceinline__ ull add2(ull a, ull b) {
    ull d; asm("add.rn.f32x2 %0, %1, %2;" : "=l"(d) : "l"(a), "l"(b)); return d;
}
__device__ __forceinline__ ull fma2(ull a, ull b, ull c) {
    ull d; asm("fma.rn.f32x2 %0, %1, %2, %3;" : "=l"(d) : "l"(a), "l"(b), "l"(c)); return d;
}

__device__ __forceinline__ float blockReduceSum(float v) {
    __shared__ float warpsum[32];
    int lane = threadIdx.x & 31;
    int wid  = threadIdx.x >> 5;
    #pragma unroll
    for (int o = 16; o > 0; o >>= 1) v += __shfl_down_sync(0xffffffffu, v, o);
    if (lane == 0) warpsum[wid] = v;
    __syncthreads();
    int nwarps = (blockDim.x + 31) >> 5;
    v = ((int)threadIdx.x < nwarps) ? warpsum[threadIdx.x] : 0.0f;
    if (wid == 0) {
        #pragma unroll
        for (int o = 16; o > 0; o >>= 1) v += __shfl_down_sync(0xffffffffu, v, o);
    }
    __syncthreads();   // protect warpsum reuse across calls
    return v;  // valid in thread 0
}

__device__ __forceinline__ float2 blockReduceSum2(float a, float b) {
    __shared__ float2 ws[32];
    int lane = threadIdx.x & 31;
    int wid  = threadIdx.x >> 5;
    #pragma unroll
    for (int o = 16; o > 0; o >>= 1) {
        a += __shfl_down_sync(0xffffffffu, a, o);
        b += __shfl_down_sync(0xffffffffu, b, o);
    }
    if (lane == 0) ws[wid] = make_float2(a, b);
    __syncthreads();
    int nwarps = (blockDim.x + 31) >> 5;
    a = ((int)threadIdx.x < nwarps) ? ws[threadIdx.x].x : 0.0f;
    b = ((int)threadIdx.x < nwarps) ? ws[threadIdx.x].y : 0.0f;
    if (wid == 0) {
        #pragma unroll
        for (int o = 16; o > 0; o >>= 1) {
            a += __shfl_down_sync(0xffffffffu, a, o);
            b += __shfl_down_sync(0xffffffffu, b, o);
        }
    }
    __syncthreads();
    return make_float2(a, b);  // valid in thread 0
}

// ================= fused persistent kernel (D == 3) =================
// f32x2 lanes hold TWO CLUSTERS (2j, 2j+1). Warp-item v:
//   hit group (v>>1): 96 contiguous hits (3 per thread -> LDS amortized x3)
//   K-half   (v&1) : uniform across warp (table LDS stays broadcast)
// 2 items per group -> ~2x warps vs R9 for latency hiding.
__global__ void __launch_bounds__(TB_MAIN, 2)
k_fused3(const float* __restrict__ x, const float* __restrict__ beta,
         const int* __restrict__ y, const int* __restrict__ Kp,
         const float* __restrict__ Sbp, const float* __restrict__ qminp,
         float* __restrict__ out, int N) {
    // Pair tables (KMAX/2 pairs): per pair CXY (16B), CZC (16B), Q (8B). 28KB total.
    __shared__ ull        s_packA[KMAX];            // 8KB  (phase A only)
    __shared__ ulonglong2 s_cxy[KMAX / 2];          // {CX,CY} 8KB
    __shared__ ulonglong2 s_czc[KMAX / 2];          // {CZ,C3} 8KB
    __shared__ ull        s_q[KMAX / 2];            // {q2j,q2j+1} 4KB

    int   K    = Kp    ? __ldg(Kp)    : 256;
    float qmin = qminp ? __ldg(qminp) : 0.5f;
    int   Kp2  = (K + 1) & ~1;     // padded even
    int   NP   = Kp2 >> 1;         // number of cluster pairs
    int   NPH  = (NP + 1) >> 1;    // pairs per half

    // ---------------- Phase A: scan (contiguous hit chunk per block) ----------------
    int chunkA = (N + gridDim.x - 1) / gridDim.x;
    int a0 = blockIdx.x * chunkA;
    int a1 = a0 + chunkA; if (a1 > N) a1 = N;

    for (int k = threadIdx.x; k < K; k += blockDim.x) s_packA[k] = 0ull;
    __syncthreads();

    float bg = 0.0f, cnt = 0.0f;
    for (int i = a0 + threadIdx.x; i < a1; i += blockDim.x) {
        int   yi = y[i];
        float b  = beta[i];
        if (yi >= 0) {
            ull p = ((ull)__float_as_uint(b) << 32) |
                    (ull)(0xFFFFFFFFu - (unsigned)i);
            atomicMax(&s_packA[yi], p);
        } else {
            bg += b; cnt += 1.0f;
        }
    }
    __syncthreads();
    for (int k = threadIdx.x; k < K; k += blockDim.x) {
        ull p = s_packA[k];
        if (p) atomicMax(&g_pack[k], p);
    }
    {
        float2 r = blockReduceSum2(bg, cnt);
        if (threadIdx.x == 0) {
            if (r.x != 0.0f) atomicAdd(&g_sum_bg, (double)r.x);
            if (r.y != 0.0f) atomicAdd(&g_cnt_bg, (double)r.y);
        }
    }

    // ---------------- grid barrier ----------------
    if (threadIdx.x == 0) {
        __threadfence();
        atomicAdd(&g_bar_cnt, 1u);
        while (atomicAdd(&g_bar_cnt, 0u) < gridDim.x) { }
        __threadfence();
    }
    __syncthreads();

    // ---------------- Phase B: build pair-packed coefficient table ----------------
    // d - 1 = cx*hx + cy*hy + cz*hz + (c3 + |h|^2),  cx = -2*xa.x,  c3 = |xa|^2 - 1.
    for (int k = threadIdx.x; k < Kp2; k += blockDim.x) {
        float q = 0.0f, cx = 0.0f, cy = 0.0f, cz = 0.0f, c3 = -1.0f;
        if (k < K) {
            ull p = __ldcg(&g_pack[k]);
            unsigned idx = 0u;
            if (p != 0ull) {
                float b = __uint_as_float((unsigned)(p >> 32));
                float a = atanhf(b);
                q = fmaf(a, a, qmin);
                idx = 0xFFFFFFFFu - (unsigned)p;
            }
            float xa = x[(size_t)idx * 3 + 0];
            float ya = x[(size_t)idx * 3 + 1];
            float za = x[(size_t)idx * 3 + 2];
            cx = -2.0f * xa; cy = -2.0f * ya; cz = -2.0f * za;
            c3 = fmaf(xa, xa, fmaf(ya, ya, za * za)) - 1.0f;
        }
        // scalar writes into packed pair layout (pair j = k>>1, lane = k&1)
        int j = k >> 1, lane = k & 1;
        float* cxyf = reinterpret_cast<float*>(&s_cxy[j]);
        float* czcf = reinterpret_cast<float*>(&s_czc[j]);
        float* qf   = reinterpret_cast<float*>(&s_q[j]);
        cxyf[lane]     = cx;   // CX lanes
        cxyf[2 + lane] = cy;   // CY lanes
        czcf[lane]     = cz;   // CZ lanes
        czcf[2 + lane] = c3;   // C3 lanes
        qf[lane]       = q;
    }
    __syncthreads();

    // ---------------- Phase B: potential sum (warp-items: 96 hits x K-half) --------
    int lane  = threadIdx.x & 31;
    int wrp   = threadIdx.x >> 5;
    int nwarp = blockDim.x >> 5;
    int GH    = 32 * THIT;                         // hits per group

    int groups  = (N + GH - 1) / GH;
    int totalWI = 2 * groups;                      // 2 K-halves per group
    int gwarp   = blockIdx.x * nwarp + wrp;        // global warp id
    int gwn     = gridDim.x * nwarp;

    float val = 0.0f;
    for (int v = gwarp; v < totalWI; v += gwn) {
        int grp  = v >> 1;
        int half = v & 1;                          // uniform across warp
        int hbase = grp * GH;

        int   yv[THIT];
        float qv[THIT];
        ull   Xv[THIT], Yv[THIT], Zv[THIT], Bv[THIT];
        float hxv[THIT], hyv[THIT], hzv[THIT], bsv[THIT];

        #pragma unroll
        for (int t = 0; t < THIT; ++t) {
            int i = hbase + lane + t * 32;
            bool ok = (i < N);
            int ic = ok ? i : (N - 1);             // safe clamp
            float hx = x[(size_t)ic * 3 + 0];
            float hy = x[(size_t)ic * 3 + 1];
            float hz = x[(size_t)ic * 3 + 2];
            yv[t] = ok ? y[ic] : -1;
            float b = beta[ic], at = atanhf(b);
            qv[t] = ok ? fmaf(at, at, qmin) : 0.0f;   // invalid -> contributes 0
            float bs = fmaf(hx, hx, fmaf(hy, hy, hz * hz));
            hxv[t] = hx; hyv[t] = hy; hzv[t] = hz; bsv[t] = bs;
            Xv[t] = pack2(hx, hx); Yv[t] = pack2(hy, hy);
            Zv[t] = pack2(hz, hz); Bv[t] = pack2(bs, bs);
        }

        float a0[THIT], a1[THIT];
        #pragma unroll
        for (int t = 0; t < THIT; ++t) { a0[t] = 0.0f; a1[t] = 0.0f; }

        int j0 = half * NPH;
        int j1 = j0 + NPH; if (j1 > NP) j1 = NP;

        #pragma unroll 4
        for (int j = j0; j < j1; ++j) {
            ulonglong2 t0 = s_cxy[j];
            ulonglong2 t1 = s_czc[j];
            ull Q = s_q[j];
            float q0, q1;
            unpack2(Q, q0, q1);
            #pragma unroll
            for (int t = 0; t < THIT; ++t) {
                // m = d - 1 for clusters 2j (lo) and 2j+1 (hi)
                ull m = fma2(t0.x, Xv[t],
                        fma2(t0.y, Yv[t],
                        fma2(t1.x, Zv[t], add2(t1.y, Bv[t]))));
                float m0, m1;
                unpack2(m, m0, m1);
                float r0 = fmaxf(-m0, 0.0f);   // max(1-d, 0)  (FMNMX: alu pipe)
                float r1 = fmaxf(-m1, 0.0f);
                a0[t] = fmaf(r0, q0, a0[t]);
                a1[t] = fmaf(r1, q1, a1[t]);
            }
        }

        #pragma unroll
        for (int t = 0; t < THIT; ++t) {
            float s = a0[t] + a1[t];
            int yi = yv[t];
            // member correction (once per hit, by half 0):
            // own-cluster term is attractive d*q, not max(1-d,0)*q
            if (half == 0 && (unsigned)yi < (unsigned)K) {
                int j = yi >> 1, ln = yi & 1;
                const float* cxyf = reinterpret_cast<const float*>(&s_cxy[j]);
                const float* czcf = reinterpret_cast<const float*>(&s_czc[j]);
                const float* qf   = reinterpret_cast<const float*>(&s_q[j]);
                float cx = cxyf[ln], cy = cxyf[2 + ln];
                float cz = czcf[ln], c3 = czcf[2 + ln];
                float qk = qf[ln];
                float m = fmaf(cx, hxv[t], fmaf(cy, hyv[t],
                          fmaf(cz, hzv[t], c3 + bsv[t])));
                s += (m + 1.0f - fmaxf(-m, 0.0f)) * qk;
            }
            val += s * qv[t];
        }
    }

    float bs = blockReduceSum(val);

    // ---------------- finalize + state reset (last block) ----------------
    __shared__ int s_last;
    if (threadIdx.x == 0) {
        atomicAdd(&g_sum_perhit, (double)bs);
        __threadfence();
        unsigned old = atomicAdd(&g_done, 1u);
        s_last = (old == gridDim.x - 1) ? 1 : 0;
    }
    __syncthreads();
    if (s_last) {
        // each thread reads-then-zeros its OWN strided elements (race-free)
        float local = 0.0f;
        for (int k = threadIdx.x; k < K; k += blockDim.x) {
            ull p = __ldcg(&g_pack[k]);
            local += 1.0f - __uint_as_float((unsigned)(p >> 32));
            g_pack[k] = 0ull;
        }
        float sbeta = blockReduceSum(local);
        if (threadIdx.x == 0) {
            float Sb = Sbp ? __ldg(Sbp) : 1.0f;
            double sum_bg = atomicAdd(&g_sum_bg, 0.0);
            double cnt_bg = atomicAdd(&g_cnt_bg, 0.0);
            double sum_ph = atomicAdd(&g_sum_perhit, 0.0);
            if (cnt_bg < 1.0) cnt_bg = 1.0;
            double L = (double)sbeta / (double)K
                     + ((double)Sb / cnt_bg) * sum_bg
                     + sum_ph / (double)N;
            out[0] = (float)L;
            // restore zero-state invariant for next graph replay
            g_sum_bg = 0.0; g_cnt_bg = 0.0; g_sum_perhit = 0.0;
            g_bar_cnt = 0u; g_done = 0u;
        }
        __threadfence();
    }
}

// ================= generic-D fallback (multi-launch) =================
__global__ void k_init() {
    int k = blockIdx.x * blockDim.x + threadIdx.x;
    if (k < KMAX) g_pack[k] = 0ull;
    if (k == 0) { g_sum_bg = 0.0; g_cnt_bg = 0.0; g_sum_perhit = 0.0; g_bar_cnt = 0u; g_done = 0u; }
}

__global__ void k_scan(const float* __restrict__ beta, const int* __restrict__ y, int N) {
    __shared__ ull sh[KMAX];
    for (int k = threadIdx.x; k < KMAX; k += blockDim.x) sh[k] = 0ull;
    __syncthreads();
    float bg = 0.0f, cnt = 0.0f;
    int stride = gridDim.x * blockDim.x;
    for (int i = blockIdx.x * blockDim.x + threadIdx.x; i < N; i += stride) {
        int   yi = y[i];
        float b  = beta[i];
        if (yi >= 0) {
            ull p = ((ull)__float_as_uint(b) << 32) | (ull)(0xFFFFFFFFu - (unsigned)i);
            atomicMax(&sh[yi], p);
        } else { bg += b; cnt += 1.0f; }
    }
    __syncthreads();
    for (int k = threadIdx.x; k < KMAX; k += blockDim.x) {
        ull p = sh[k];
        if (p) atomicMax(&g_pack[k], p);
    }
    float2 r = blockReduceSum2(bg, cnt);
    if (threadIdx.x == 0) {
        if (r.x != 0.0f) atomicAdd(&g_sum_bg, (double)r.x);
        if (r.y != 0.0f) atomicAdd(&g_cnt_bg, (double)r.y);
    }
}

__global__ void k_mainD(const float* __restrict__ x, const float* __restrict__ beta,
                        const int* __restrict__ y, const int* __restrict__ Kp,
                        const float* __restrict__ qminp, int N, int D) {
    extern __shared__ float sm[];
    int   K    = Kp    ? __ldg(Kp)    : 256;
    float qmin = qminp ? __ldg(qminp) : 0.5f;
    float* s_qf = sm;
    float* s_xa = sm + K;
    for (int k = threadIdx.x; k < K; k += blockDim.x) {
        ull p = g_pack[k];
        float q = 0.0f; unsigned idx = 0u;
        if (p != 0ull) {
            float b = __uint_as_float((unsigned)(p >> 32));
            float a = atanhf(b);
            q = fmaf(a, a, qmin);
            idx = 0xFFFFFFFFu - (unsigned)p;
        }
        s_qf[k] = q;
        for (int d = 0; d < D; ++d) s_xa[k * D + d] = x[(size_t)idx * D + d];
    }
    __syncthreads();
    int i = blockIdx.x * blockDim.x + threadIdx.x;
    float val = 0.0f;
    if (i < N) {
        int   yi = y[i];
        float b = beta[i], a = atanhf(b);
        float qi = fmaf(a, a, qmin);
        float acc = 0.0f;
        for (int k = 0; k < K; ++k) {
            float d = 0.0f;
            for (int dd = 0; dd < D; ++dd) {
                float t = x[(size_t)i * D + dd] - s_xa[k * D + dd];
                d = fmaf(t, t, d);
            }
            float t = (k == yi) ? d : fmaxf(1.0f - d, 0.0f);
            acc = fmaf(t, s_qf[k], acc);
        }
        val = acc * qi;
    }
    float bs = blockReduceSum(val);
    if (threadIdx.x == 0) atomicAdd(&g_sum_perhit, (double)bs);
}

__global__ void k_final(const int* __restrict__ Kp, const float* __restrict__ Sbp,
                        float* __restrict__ out, int N) {
    int   K  = Kp  ? __ldg(Kp)  : 256;
    float Sb = Sbp ? __ldg(Sbp) : 1.0f;
    float local = 0.0f;
    for (int k = threadIdx.x; k < K; k += blockDim.x) {
        ull p = g_pack[k];
        local += 1.0f - __uint_as_float((unsigned)(p >> 32));
    }
    float s = blockReduceSum(local);
    if (threadIdx.x == 0) {
        double Nb = g_cnt_bg;
        if (Nb < 1.0) Nb = 1.0;
        double L = (double)s / (double)K
                 + ((double)Sb / Nb) * g_sum_bg
                 + g_sum_perhit / (double)N;
        out[0] = (float)L;
    }
}

extern "C" void kernel_launch(void* const* d_in, const int* in_sizes, int n_in,
                              void* d_out, int out_size) {
    const float* x    = (const float*)d_in[0];
    const float* beta = (const float*)d_in[1];
    const int*   y    = (const int*)d_in[2];
    const int*   Kp   = (n_in > 3) ? (const int*)d_in[3]   : nullptr;
    const float* Sbp  = (n_in > 4) ? (const float*)d_in[4] : nullptr;
    const float* qmp  = (n_in > 5) ? (const float*)d_in[5] : nullptr;

    int N = in_sizes[1];
    int D = (N > 0) ? (in_sizes[0] / N) : 3;
    float* out = (float*)d_out;

    if (D == 3) {
        k_fused3<<<NBLK, TB_MAIN>>>(x, beta, y, Kp, Sbp, qmp, out, N);
    } else {
        k_init<<<(KMAX + 255) / 256, 256>>>();
        k_scan<<<148, 256>>>(beta, y, N);
        int blocks = (N + 255) / 256;
        size_t smem = (size_t)KMAX * (1 + (size_t)D) * sizeof(float);
        k_mainD<<<blocks, 256, smem>>>(x, beta, y, Kp, qmp, N, D);
        k_final<<<1, 256>>>(Kp, Sbp, out, N);
        // restore zero-state invariant for the fused path's assumptions
        k_init<<<(KMAX + 255) / 256, 256>>>();
    }
    (void)out_size;
}

// round 12
// speedup vs baseline: 1.1216x; 1.1216x over previous
#include <cuda_runtime.h>
#include <cuda_bf16.h>

// ObjCondensationLoss — single fused persistent kernel (D==3 fast path).
// Inputs: x (N*3 f32), beta (N f32), y (N i32), K (i32), S_b (f32), q_min (f32)
// Output: scalar f32 loss.
//
// Invariant: all __device__ globals below are ZERO at kernel entry (zero at
// module load; the finalizing block restores zeros before exit each call).

#define KMAX    1024
#define TB_MAIN 256
#define NBLK    148
#define THIT    3      // hits per thread per macro-trip (amortizes table LDS)

typedef unsigned long long ull;

// pack = (beta_bits << 32) | (0xFFFFFFFF - i). beta>0 => float-bit order == value
// order; atanh monotone => argmax(q) == argmax(beta); tie -> smallest index.
__device__ ull      g_pack[KMAX];
__device__ double   g_sum_bg;      // sum beta over background hits
__device__ double   g_cnt_bg;      // N_b
__device__ double   g_sum_perhit;  // sum(per_hit * q_i)
__device__ unsigned g_bar_cnt;     // grid barrier counter
__device__ unsigned g_done;        // finalize counter

// ---------- f32x2 packed helpers ----------
__device__ __forceinline__ ull pack2(float lo, float hi) {
    ull r; asm("mov.b64 %0, {%1, %2};" : "=l"(r) : "f"(lo), "f"(hi)); return r;
}
__device__ __forceinline__ void unpack2(ull v, float& lo, float& hi) {
    asm("mov.b64 {%0, %1}, %2;" : "=f"(lo), "=f"(hi) : "l"(v));
}
__device__ __forceinline__ ull add2(ull a, ull b) {
    ull d; asm("add.rn.f32x2 %0, %1, %2;" : "=l"(d) : "l"(a), "l"(b)); return d;
}
__device__ __forceinline__ ull fma2(ull a, ull b, ull c) {
    ull d; asm("fma.rn.f32x2 %0, %1, %2, %3;" : "=l"(d) : "l"(a), "l"(b), "l"(c)); return d;
}
// per-lane relu on a packed f32x2 (2 scalar max.f32 on the register pair;
// the mov.b64 pack/unpack are register-pairing pseudo-ops)
__device__ __forceinline__ ull relu2(ull u) {
    ull r;
    asm("{\n\t"
        ".reg .f32 lo, hi;\n\t"
        "mov.b64 {lo, hi}, %1;\n\t"
        "max.f32 lo, lo, 0f00000000;\n\t"
        "max.f32 hi, hi, 0f00000000;\n\t"
        "mov.b64 %0, {lo, hi};\n\t"
        "}" : "=l"(r) : "l"(u));
    return r;
}

__device__ __forceinline__ float blockReduceSum(float v) {
    __shared__ float warpsum[32];
    int lane = threadIdx.x & 31;
    int wid  = threadIdx.x >> 5;
    #pragma unroll
    for (int o = 16; o > 0; o >>= 1) v += __shfl_down_sync(0xffffffffu, v, o);
    if (lane == 0) warpsum[wid] = v;
    __syncthreads();
    int nwarps = (blockDim.x + 31) >> 5;
    v = ((int)threadIdx.x < nwarps) ? warpsum[threadIdx.x] : 0.0f;
    if (wid == 0) {
        #pragma unroll
        for (int o = 16; o > 0; o >>= 1) v += __shfl_down_sync(0xffffffffu, v, o);
    }
    __syncthreads();   // protect warpsum reuse across calls
    return v;  // valid in thread 0
}

__device__ __forceinline__ float2 blockReduceSum2(float a, float b) {
    __shared__ float2 ws[32];
    int lane = threadIdx.x & 31;
    int wid  = threadIdx.x >> 5;
    #pragma unroll
    for (int o = 16; o > 0; o >>= 1) {
        a += __shfl_down_sync(0xffffffffu, a, o);
        b += __shfl_down_sync(0xffffffffu, b, o);
    }
    if (lane == 0) ws[wid] = make_float2(a, b);
    __syncthreads();
    int nwarps = (blockDim.x + 31) >> 5;
    a = ((int)threadIdx.x < nwarps) ? ws[threadIdx.x].x : 0.0f;
    b = ((int)threadIdx.x < nwarps) ? ws[threadIdx.x].y : 0.0f;
    if (wid == 0) {
        #pragma unroll
        for (int o = 16; o > 0; o >>= 1) {
            a += __shfl_down_sync(0xffffffffu, a, o);
            b += __shfl_down_sync(0xffffffffu, b, o);
        }
    }
    __syncthreads();
    return make_float2(a, b);  // valid in thread 0
}

// ================= fused persistent kernel (D == 3) =================
// f32x2 lanes hold TWO CLUSTERS (2j, 2j+1). Each thread processes THIT hits
// per macro-trip so each table LDS is amortized over THIT hits.
// Algebra: u = 1 - d = px*hx + py*hy + pz*hz + (p3 - |h|^2),
//   px = 2*xa.x, p3 = 1 - |xa|^2.  Repulsive term = relu(u)*q.
__global__ void __launch_bounds__(TB_MAIN)
k_fused3(const float* __restrict__ x, const float* __restrict__ beta,
         const int* __restrict__ y, const int* __restrict__ Kp,
         const float* __restrict__ Sbp, const float* __restrict__ qminp,
         float* __restrict__ out, int N) {
    // Pair tables (KMAX/2 pairs): per pair PXY (16B), PZC (16B), Q (8B). 28KB total.
    __shared__ ull        s_packA[KMAX];            // 8KB  (phase A only)
    __shared__ ulonglong2 s_pxy[KMAX / 2];          // {PX,PY} 8KB
    __shared__ ulonglong2 s_pzc[KMAX / 2];          // {PZ,P3} 8KB
    __shared__ ull        s_q[KMAX / 2];            // {q2j,q2j+1} 4KB

    int   K    = Kp    ? __ldg(Kp)    : 256;
    float qmin = qminp ? __ldg(qminp) : 0.5f;
    int   Kp2  = (K + 1) & ~1;     // padded even
    int   NP   = Kp2 >> 1;         // number of cluster pairs

    // per-block contiguous chunk [c0, c1)
    int chunk = (N + gridDim.x - 1) / gridDim.x;
    int c0 = blockIdx.x * chunk;
    int c1 = c0 + chunk; if (c1 > N) c1 = N;

    // ---------------- Phase A: scan ----------------
    for (int k = threadIdx.x; k < K; k += blockDim.x) s_packA[k] = 0ull;
    __syncthreads();

    float bg = 0.0f, cnt = 0.0f;
    for (int i = c0 + threadIdx.x; i < c1; i += blockDim.x) {
        int   yi = y[i];
        float b  = beta[i];
        if (yi >= 0) {
            ull p = ((ull)__float_as_uint(b) << 32) |
                    (ull)(0xFFFFFFFFu - (unsigned)i);
            atomicMax(&s_packA[yi], p);
        } else {
            bg += b; cnt += 1.0f;
        }
    }
    __syncthreads();
    for (int k = threadIdx.x; k < K; k += blockDim.x) {
        ull p = s_packA[k];
        if (p) atomicMax(&g_pack[k], p);
    }
    {
        float2 r = blockReduceSum2(bg, cnt);
        if (threadIdx.x == 0) {
            if (r.x != 0.0f) atomicAdd(&g_sum_bg, (double)r.x);
            if (r.y != 0.0f) atomicAdd(&g_cnt_bg, (double)r.y);
        }
    }

    // ---------------- grid barrier ----------------
    if (threadIdx.x == 0) {
        __threadfence();
        atomicAdd(&g_bar_cnt, 1u);
        while (atomicAdd(&g_bar_cnt, 0u) < gridDim.x) { }
        __threadfence();
    }
    __syncthreads();

    // ---------------- Phase B: build pair-packed coefficient table ----------------
    for (int k = threadIdx.x; k < Kp2; k += blockDim.x) {
        float q = 0.0f, px = 0.0f, py = 0.0f, pz = 0.0f, p3 = 0.0f;
        if (k < K) {
            ull p = __ldcg(&g_pack[k]);
            unsigned idx = 0u;
            if (p != 0ull) {
                float b = __uint_as_float((unsigned)(p >> 32));
                float a = atanhf(b);
                q = fmaf(a, a, qmin);
                idx = 0xFFFFFFFFu - (unsigned)p;
            }
            float xa = x[(size_t)idx * 3 + 0];
            float ya = x[(size_t)idx * 3 + 1];
            float za = x[(size_t)idx * 3 + 2];
            px = 2.0f * xa; py = 2.0f * ya; pz = 2.0f * za;
            p3 = 1.0f - fmaf(xa, xa, fmaf(ya, ya, za * za));
        }
        // scalar writes into packed pair layout (pair j = k>>1, lane = k&1)
        int j = k >> 1, lane = k & 1;
        float* pxyf = reinterpret_cast<float*>(&s_pxy[j]);
        float* pzcf = reinterpret_cast<float*>(&s_pzc[j]);
        float* qf   = reinterpret_cast<float*>(&s_q[j]);
        pxyf[lane]     = px;   // PX lanes
        pxyf[2 + lane] = py;   // PY lanes
        pzcf[lane]     = pz;   // PZ lanes
        pzcf[2 + lane] = p3;   // P3 lanes
        qf[lane]       = q;
    }
    __syncthreads();

    // ---------------- Phase B: potential sum (THIT hits / thread) ----------------
    float val = 0.0f;
    for (int base = c0; base < c1; base += THIT * TB_MAIN) {
        int   yv[THIT];
        float qv[THIT];
        ull   Xv[THIT], Yv[THIT], Zv[THIT], Bv[THIT];
        float hxv[THIT], hyv[THIT], hzv[THIT], bsv[THIT];

        #pragma unroll
        for (int t = 0; t < THIT; ++t) {
            int i = base + threadIdx.x + t * TB_MAIN;
            bool ok = (i < c1);
            int ic = ok ? i : c0;                 // safe clamp
            float hx = x[(size_t)ic * 3 + 0];
            float hy = x[(size_t)ic * 3 + 1];
            float hz = x[(size_t)ic * 3 + 2];
            yv[t] = ok ? y[ic] : -1;
            float b = beta[ic], at = atanhf(b);
            qv[t] = ok ? fmaf(at, at, qmin) : 0.0f;  // invalid -> contributes 0
            float bs = fmaf(hx, hx, fmaf(hy, hy, hz * hz));
            hxv[t] = hx; hyv[t] = hy; hzv[t] = hz; bsv[t] = bs;
            Xv[t] = pack2(hx, hx); Yv[t] = pack2(hy, hy);
            Zv[t] = pack2(hz, hz); Bv[t] = pack2(-bs, -bs);
        }

        ull acc[THIT];
        #pragma unroll
        for (int t = 0; t < THIT; ++t) acc[t] = 0ull;   // {0.0f, 0.0f}

        // software-pipelined table loads (prefetch j+1; reading one entry past
        // NP stays inside the fixed-size shared arrays, value unused)
        ulonglong2 nt0 = s_pxy[0];
        ulonglong2 nt1 = s_pzc[0];
        ull        nq  = s_q[0];

        #pragma unroll 8
        for (int j = 0; j < NP; ++j) {
            ulonglong2 t0 = nt0;
            ulonglong2 t1 = nt1;
            ull        Q  = nq;
            nt0 = s_pxy[j + 1];
            nt1 = s_pzc[j + 1];
            nq  = s_q[j + 1];
            #pragma unroll
            for (int t = 0; t < THIT; ++t) {
                // u = 1 - d for clusters 2j (lo) and 2j+1 (hi)
                ull u = fma2(t0.x, Xv[t],
                        fma2(t0.y, Yv[t],
                        fma2(t1.x, Zv[t], add2(t1.y, Bv[t]))));
                acc[t] = fma2(relu2(u), Q, acc[t]);   // packed relu + accumulate
            }
        }

        #pragma unroll
        for (int t = 0; t < THIT; ++t) {
            float s0, s1;
            unpack2(acc[t], s0, s1);
            float s = s0 + s1;
            int yi = yv[t];
            // member correction: own-cluster term is attractive d*q = (1-u)*q,
            // replacing the repulsive relu(u)*q added in the loop.
            if ((unsigned)yi < (unsigned)K) {
                int j = yi >> 1, ln = yi & 1;
                const float* pxyf = reinterpret_cast<const float*>(&s_pxy[j]);
                const float* pzcf = reinterpret_cast<const float*>(&s_pzc[j]);
                const float* qf   = reinterpret_cast<const float*>(&s_q[j]);
                float px = pxyf[ln], py = pxyf[2 + ln];
                float pz = pzcf[ln], p3 = pzcf[2 + ln];
                float qk = qf[ln];
                float u = fmaf(px, hxv[t], fmaf(py, hyv[t],
                          fmaf(pz, hzv[t], p3 - bsv[t])));
                s += ((1.0f - u) - fmaxf(u, 0.0f)) * qk;
            }
            val += s * qv[t];
        }
    }

    float bs = blockReduceSum(val);

    // ---------------- finalize + state reset (last block) ----------------
    __shared__ int s_last;
    if (threadIdx.x == 0) {
        atomicAdd(&g_sum_perhit, (double)bs);
        __threadfence();
        unsigned old = atomicAdd(&g_done, 1u);
        s_last = (old == gridDim.x - 1) ? 1 : 0;
    }
    __syncthreads();
    if (s_last) {
        // each thread reads-then-zeros its OWN strided elements (race-free)
        float local = 0.0f;
        for (int k = threadIdx.x; k < K; k += blockDim.x) {
            ull p = __ldcg(&g_pack[k]);
            local += 1.0f - __uint_as_float((unsigned)(p >> 32));
            g_pack[k] = 0ull;
        }
        float sbeta = blockReduceSum(local);
        if (threadIdx.x == 0) {
            float Sb = Sbp ? __ldg(Sbp) : 1.0f;
            double sum_bg = atomicAdd(&g_sum_bg, 0.0);
            double cnt_bg = atomicAdd(&g_cnt_bg, 0.0);
            double sum_ph = atomicAdd(&g_sum_perhit, 0.0);
            if (cnt_bg < 1.0) cnt_bg = 1.0;
            double L = (double)sbeta / (double)K
                     + ((double)Sb / cnt_bg) * sum_bg
                     + sum_ph / (double)N;
            out[0] = (float)L;
            // restore zero-state invariant for next graph replay
            g_sum_bg = 0.0; g_cnt_bg = 0.0; g_sum_perhit = 0.0;
            g_bar_cnt = 0u; g_done = 0u;
        }
        __threadfence();
    }
}

// ================= generic-D fallback (multi-launch) =================
__global__ void k_init() {
    int k = blockIdx.x * blockDim.x + threadIdx.x;
    if (k < KMAX) g_pack[k] = 0ull;
    if (k == 0) { g_sum_bg = 0.0; g_cnt_bg = 0.0; g_sum_perhit = 0.0; g_bar_cnt = 0u; g_done = 0u; }
}

__global__ void k_scan(const float* __restrict__ beta, const int* __restrict__ y, int N) {
    __shared__ ull sh[KMAX];
    for (int k = threadIdx.x; k < KMAX; k += blockDim.x) sh[k] = 0ull;
    __syncthreads();
    float bg = 0.0f, cnt = 0.0f;
    int stride = gridDim.x * blockDim.x;
    for (int i = blockIdx.x * blockDim.x + threadIdx.x; i < N; i += stride) {
        int   yi = y[i];
        float b  = beta[i];
        if (yi >= 0) {
            ull p = ((ull)__float_as_uint(b) << 32) | (ull)(0xFFFFFFFFu - (unsigned)i);
            atomicMax(&sh[yi], p);
        } else { bg += b; cnt += 1.0f; }
    }
    __syncthreads();
    for (int k = threadIdx.x; k < KMAX; k += blockDim.x) {
        ull p = sh[k];
        if (p) atomicMax(&g_pack[k], p);
    }
    float2 r = blockReduceSum2(bg, cnt);
    if (threadIdx.x == 0) {
        if (r.x != 0.0f) atomicAdd(&g_sum_bg, (double)r.x);
        if (r.y != 0.0f) atomicAdd(&g_cnt_bg, (double)r.y);
    }
}

__global__ void k_mainD(const float* __restrict__ x, const float* __restrict__ beta,
                        const int* __restrict__ y, const int* __restrict__ Kp,
                        const float* __restrict__ qminp, int N, int D) {
    extern __shared__ float sm[];
    int   K    = Kp    ? __ldg(Kp)    : 256;
    float qmin = qminp ? __ldg(qminp) : 0.5f;
    float* s_qf = sm;
    float* s_xa = sm + K;
    for (int k = threadIdx.x; k < K; k += blockDim.x) {
        ull p = g_pack[k];
        float q = 0.0f; unsigned idx = 0u;
        if (p != 0ull) {
            float b = __uint_as_float((unsigned)(p >> 32));
            float a = atanhf(b);
            q = fmaf(a, a, qmin);
            idx = 0xFFFFFFFFu - (unsigned)p;
        }
        s_qf[k] = q;
        for (int d = 0; d < D; ++d) s_xa[k * D + d] = x[(size_t)idx * D + d];
    }
    __syncthreads();
    int i = blockIdx.x * blockDim.x + threadIdx.x;
    float val = 0.0f;
    if (i < N) {
        int   yi = y[i];
        float b = beta[i], a = atanhf(b);
        float qi = fmaf(a, a, qmin);
        float acc = 0.0f;
        for (int k = 0; k < K; ++k) {
            float d = 0.0f;
            for (int dd = 0; dd < D; ++dd) {
                float t = x[(size_t)i * D + dd] - s_xa[k * D + dd];
                d = fmaf(t, t, d);
            }
            float t = (k == yi) ? d : fmaxf(1.0f - d, 0.0f);
            acc = fmaf(t, s_qf[k], acc);
        }
        val = acc * qi;
    }
    float bs = blockReduceSum(val);
    if (threadIdx.x == 0) atomicAdd(&g_sum_perhit, (double)bs);
}

__global__ void k_final(const int* __restrict__ Kp, const float* __restrict__ Sbp,
                        float* __restrict__ out, int N) {
    int   K  = Kp  ? __ldg(Kp)  : 256;
    float Sb = Sbp ? __ldg(Sbp) : 1.0f;
    float local = 0.0f;
    for (int k = threadIdx.x; k < K; k += blockDim.x) {
        ull p = g_pack[k];
        local += 1.0f - __uint_as_float((unsigned)(p >> 32));
    }
    float s = blockReduceSum(local);
    if (threadIdx.x == 0) {
        double Nb = g_cnt_bg;
        if (Nb < 1.0) Nb = 1.0;
        double L = (double)s / (double)K
                 + ((double)Sb / Nb) * g_sum_bg
                 + g_sum_perhit / (double)N;
        out[0] = (float)L;
    }
}

extern "C" void kernel_launch(void* const* d_in, const int* in_sizes, int n_in,
                              void* d_out, int out_size) {
    const float* x    = (const float*)d_in[0];
    const float* beta = (const float*)d_in[1];
    const int*   y    = (const int*)d_in[2];
    const int*   Kp   = (n_in > 3) ? (const int*)d_in[3]   : nullptr;
    const float* Sbp  = (n_in > 4) ? (const float*)d_in[4] : nullptr;
    const float* qmp  = (n_in > 5) ? (const float*)d_in[5] : nullptr;

    int N = in_sizes[1];
    int D = (N > 0) ? (in_sizes[0] / N) : 3;
    float* out = (float*)d_out;

    if (D == 3) {
        k_fused3<<<NBLK, TB_MAIN>>>(x, beta, y, Kp, Sbp, qmp, out, N);
    } else {
        k_init<<<(KMAX + 255) / 256, 256>>>();
        k_scan<<<148, 256>>>(beta, y, N);
        int blocks = (N + 255) / 256;
        size_t smem = (size_t)KMAX * (1 + (size_t)D) * sizeof(float);
        k_mainD<<<blocks, 256, smem>>>(x, beta, y, Kp, qmp, N, D);
        k_final<<<1, 256>>>(Kp, Sbp, out, N);
        // restore zero-state invariant for the fused path's assumptions
        k_init<<<(KMAX + 255) / 256, 256>>>();
    }
    (void)out_size;
}